// round 16
// baseline (speedup 1.0000x reference)
#include <cuda_runtime.h>
#include <math.h>

#define BATCH 32
#define NROI 1000
#define NCLS 81
#define MAXI 100
#define NTOT (BATCH * NROI)
#define BPI 8                   // blocks per image
#define RPB 125                 // ROIs per block
#define BT 1024
#define FULL 0xffffffffu

// global scratch (zero-init; counters reset by final block each run)
__device__ float4 g_cbox[NTOT];
__device__ float4 g_cmeta[NTOT];   // {score, cls, origidx, 0}
__device__ unsigned char g_keep[NTOT];
__device__ int    g_cnt[BATCH];
__device__ int    g_done[BATCH];   // ticket 1 (phase-1 completion)
__device__ int    g_done2[BATCH];  // ticket 2 (NMS completion)

struct Epi {
    float4 box[NROI];            // 16 KB
    float  score[NROI];          // 4 KB
    short  idx[NROI];
    short  cls[NROI];
    short  perm[NROI];
    short  sortd[NROI];
    unsigned char kp[NROI];
    int    ccount[NCLS];
    int    cstart[NCLS];
    int    ccur[NCLS];
    float  k_score[NROI];
    short  k_idx[NROI];
    short  k_ent[NROI];
    float  outbuf[MAXI * 6];
};

union SmemU {
    float tile[RPB * NCLS + 4];  // 40.5 KB phase-1 tile
    Epi   ep;                    // ~38.5 KB epilogue state
};

__global__ __launch_bounds__(BT, 2)
void det_kernel(const float* __restrict__ rois,
                const float* __restrict__ probs,
                const float* __restrict__ bbox,
                const float* __restrict__ std_dev,
                float* __restrict__ out)
{
    __shared__ SmemU u;
    __shared__ int s_wsum[32];
    __shared__ int s_K;
    __shared__ int s_last;

    const int img = blockIdx.x / BPI;
    const int sub = blockIdx.x - img * BPI;
    const int t   = threadIdx.x;
    const int wid = t >> 5;
    const int lane = t & 31;

    // ================= Phase 1: tile load + argmax + compact =================
    {
        const size_t s0 = ((size_t)img * NROI + sub * RPB) * NCLS;
        const int sh  = (int)(s0 & 3);
        const int NEL = RPB * NCLS;                 // 10125
        const int h   = (4 - sh) & 3;

        if (t < h) u.tile[sh + t] = probs[s0 + t];
        const int nvec = (NEL - h) >> 2;
        const float4* gp = (const float4*)(probs + s0 + h);
        float4* spv = (float4*)(u.tile + sh + h);
        const int i0 = t, i1 = t + BT, i2 = t + 2 * BT;
        const bool p0 = i0 < nvec, p1 = i1 < nvec, p2 = i2 < nvec;
        float4 a0, a1, a2;
        if (p0) a0 = gp[i0];
        if (p1) a1 = gp[i1];
        if (p2) a2 = gp[i2];
        if (p0) spv[i0] = a0;
        if (p1) spv[i1] = a1;
        if (p2) spv[i2] = a2;
        const int tl = NEL - h - 4 * nvec;
        if (t < tl) { int e = h + 4 * nvec + t; u.tile[sh + e] = probs[s0 + e]; }
        __syncthreads();

        if (t < RPB) {
            const float* row = u.tile + sh + t * NCLS;
            float b0 = row[0]; int c0 = 0;
            float b1 = row[1]; int c1 = 1;
            float b2 = row[2]; int c2 = 2;
            #pragma unroll 13
            for (int c = 3; c < 81; c += 3) {
                float v0 = row[c];
                float v1 = row[c + 1];
                float v2 = row[c + 2];
                if (v0 > b0) { b0 = v0; c0 = c; }
                if (v1 > b1) { b1 = v1; c1 = c + 1; }
                if (v2 > b2) { b2 = v2; c2 = c + 2; }
            }
            float best = b0; int bi = c0;
            if (b1 > best || (b1 == best && c1 < bi)) { best = b1; bi = c1; }
            if (b2 > best || (b2 == best && c2 < bi)) { best = b2; bi = c2; }

            if (bi > 0 && best >= 0.7f) {
                const int r = sub * RPB + t;
                const size_t gri = (size_t)img * NROI + r;
                const float4 sd = *(const float4*)std_dev;
                const float4 dv = *(const float4*)(bbox + (gri * NCLS + bi) * 4);
                const float4 ro = *(const float4*)(rois + gri * 4);

                float d0 = dv.x * sd.x, d1 = dv.y * sd.y, d2 = dv.z * sd.z, d3 = dv.w * sd.w;
                float hh = ro.z - ro.x;
                float ww = ro.w - ro.y;
                float cy = ro.x + 0.5f * hh + d0 * hh;
                float cx = ro.y + 0.5f * ww + d1 * ww;
                hh *= expf(d2);
                ww *= expf(d3);
                float ny1 = cy - 0.5f * hh;
                float nx1 = cx - 0.5f * ww;
                float ny2 = ny1 + hh;
                float nx2 = nx1 + ww;
                ny1 = fminf(fmaxf(ny1, 0.0f), 1.0f);
                nx1 = fminf(fmaxf(nx1, 0.0f), 1.0f);
                ny2 = fminf(fmaxf(ny2, 0.0f), 1.0f);
                nx2 = fminf(fmaxf(nx2, 0.0f), 1.0f);

                int pos = atomicAdd(&g_cnt[img], 1);
                if (pos < NROI) {
                    g_cbox[img * NROI + pos]  = make_float4(ny1, nx1, ny2, nx2);
                    g_cmeta[img * NROI + pos] = make_float4(best, (float)bi, (float)r, 0.0f);
                }
            }
        }
    }

    // ========== Ticket 1: wait until ALL 8 blocks of this image finish =======
    __syncthreads();
    if (t == 0) {
        __threadfence();
        atomicAdd(&g_done[img], 1);
        while (atomicAdd(&g_done[img], 0) < BPI) { }   // single wave: safe spin
    }
    __syncthreads();
    __threadfence();   // acquire: full compacted list visible

    // ========== Distributed grouping + NMS (ALL 8 blocks) =====================
    Epi& ep = u.ep;
    const int base = img * NROI;
    const int M = min(g_cnt[img], NROI);

    if (t < NCLS) { ep.ccount[t] = 0; ep.ccur[t] = 0; }
    __syncthreads();   // union transition

    int mycls = -1;
    if (t < M) {
        float4 m  = g_cmeta[base + t];    // L2-warm
        float4 bx = g_cbox[base + t];
        ep.score[t] = m.x;
        ep.cls[t]   = (short)m.y;
        ep.idx[t]   = (short)m.z;
        ep.box[t]   = bx;
        mycls = (int)m.y;
    }
    __syncthreads();
    if (mycls >= 0) atomicAdd(&ep.ccount[mycls], 1);
    __syncthreads();

    if (wid == 0) {   // warp0 shfl-scan of 81 class counts
        const int cA = lane, cB = lane + 32, cC = lane + 64;
        int v0 = ep.ccount[cA];
        int v1 = (cB < NCLS) ? ep.ccount[cB] : 0;
        int v2 = (cC < NCLS) ? ep.ccount[cC] : 0;
        int i0 = v0, i1 = v1, i2 = v2;
        #pragma unroll
        for (int off = 1; off < 32; off <<= 1) {
            int n0 = __shfl_up_sync(FULL, i0, off);
            int n1 = __shfl_up_sync(FULL, i1, off);
            int n2 = __shfl_up_sync(FULL, i2, off);
            if (lane >= off) { i0 += n0; i1 += n1; i2 += n2; }
        }
        const int tot0 = __shfl_sync(FULL, i0, 31);
        const int tot1 = __shfl_sync(FULL, i1, 31);
        ep.cstart[cA] = i0 - v0;
        if (cB < NCLS) ep.cstart[cB] = tot0 + i1 - v1;
        if (cC < NCLS) ep.cstart[cC] = tot0 + tot1 + i2 - v2;
    }
    __syncthreads();

    if (mycls >= 0) {
        int p = ep.cstart[mycls] + atomicAdd(&ep.ccur[mycls], 1);
        ep.perm[p] = (short)t;
    }
    __syncthreads();

    // ---- this block's classes: c = sub + 8*wid (one class per warp) ----
    {
        const int c = sub + BPI * wid;
        if (c < NCLS) {
            const int cs = ep.cstart[c];
            const int n  = ep.ccount[c];
            if (n > 0 && n <= 32) {
                const bool v = (lane < n);
                int e = 0; float sc = -1.0f, idf = 1e9f;
                float4 bb = make_float4(0.f, 0.f, 0.f, 0.f);
                if (v) {
                    e = ep.perm[cs + lane];
                    sc = ep.score[e]; idf = (float)ep.idx[e];
                    bb = ep.box[e];
                }
                int rank = v ? 0 : 999;
                for (int m2 = 0; m2 < n; ++m2) {
                    float s2 = __shfl_sync(FULL, sc,  m2);
                    float i2 = __shfl_sync(FULL, idf, m2);
                    if (v) rank += (s2 > sc) || (s2 == sc && i2 < idf);
                }
                int keep = v ? 1 : 0;
                float area = (bb.z - bb.x) * (bb.w - bb.y);
                for (int a = 0; a < n - 1; ++a) {
                    unsigned am = __ballot_sync(FULL, rank == a);
                    int src = __ffs(am) - 1;
                    int ks  = __shfl_sync(FULL, keep, src);
                    float sy1 = __shfl_sync(FULL, bb.x, src);
                    float sx1 = __shfl_sync(FULL, bb.y, src);
                    float sy2 = __shfl_sync(FULL, bb.z, src);
                    float sx2 = __shfl_sync(FULL, bb.w, src);
                    float sa  = __shfl_sync(FULL, area, src);
                    if (ks && keep && rank > a) {
                        float ih = fmaxf(fminf(sy2, bb.z) - fmaxf(sy1, bb.x), 0.0f);
                        float iw = fmaxf(fminf(sx2, bb.w) - fmaxf(sx1, bb.y), 0.0f);
                        float inter = ih * iw;
                        float iou = inter / fmaxf(sa + area - inter, 1e-8f);
                        if (iou > 0.3f) keep = 0;
                    }
                }
                if (v) g_keep[base + e] = (unsigned char)keep;
            } else if (n > 32) {
                // smem path (rare big class): sort into sortd/kp then greedy
                for (int p = lane; p < n; p += 32) {
                    int e = ep.perm[cs + p];
                    float sc = ep.score[e]; short id = ep.idx[e];
                    int rank = 0;
                    for (int j = 0; j < n; ++j) {
                        int ej = ep.perm[cs + j];
                        float sj = ep.score[ej];
                        rank += (sj > sc) || (sj == sc && ep.idx[ej] < id);
                    }
                    ep.sortd[cs + rank] = (short)e;
                    ep.kp[cs + rank] = 1;
                }
                __syncwarp();
                for (int a = 0; a < n - 1; ++a) {
                    if (!ep.kp[cs + a]) continue;
                    int ea = ep.sortd[cs + a];
                    float4 ba = ep.box[ea];
                    float aa = (ba.z - ba.x) * (ba.w - ba.y);
                    for (int q = a + 1 + lane; q < n; q += 32) {
                        if (!ep.kp[cs + q]) continue;
                        int eq = ep.sortd[cs + q];
                        float4 bq = ep.box[eq];
                        float ab = (bq.z - bq.x) * (bq.w - bq.y);
                        float ih = fmaxf(fminf(ba.z, bq.z) - fmaxf(ba.x, bq.x), 0.0f);
                        float iw = fmaxf(fminf(ba.w, bq.w) - fmaxf(ba.y, bq.y), 0.0f);
                        float inter = ih * iw;
                        float iou = inter / fmaxf(aa + ab - inter, 1e-8f);
                        if (iou > 0.3f) ep.kp[cs + q] = 0;
                    }
                    __syncwarp();
                }
                for (int p = lane; p < n; p += 32)
                    g_keep[base + ep.sortd[cs + p]] = ep.kp[cs + p];
            }
        }
    }

    // ========== Ticket 2: last block to finish NMS emits output ==============
    __syncthreads();
    if (t == 0) {
        __threadfence();
        int tick = atomicAdd(&g_done2[img], 1);
        s_last = (tick == BPI - 1) ? 1 : 0;
    }
    __syncthreads();
    if (!s_last) return;
    __threadfence();   // acquire: all keep flags visible

    // ---- final: compact kept (ballot scan), rank = slot, emit ----
    for (int o = t; o < MAXI * 6; o += BT) ep.outbuf[o] = 0.0f;

    int kflag = 0;
    if (t < M && g_keep[base + t]) kflag = 1;
    {
        unsigned mask = __ballot_sync(FULL, kflag);
        if (lane == 0) s_wsum[wid] = __popc(mask);
        __syncthreads();
        if (wid == 0) {
            int v = s_wsum[lane];
            int inc = v;
            #pragma unroll
            for (int off = 1; off < 32; off <<= 1) {
                int nn = __shfl_up_sync(FULL, inc, off);
                if (lane >= off) inc += nn;
            }
            s_wsum[lane] = inc - v;
            if (lane == 31) s_K = inc;
        }
        __syncthreads();
        int slot = s_wsum[wid] + __popc(mask & ((1u << lane) - 1));
        if (kflag) {
            ep.k_score[slot] = ep.score[t];
            ep.k_idx[slot]   = ep.idx[t];
            ep.k_ent[slot]   = (short)t;
        }
    }
    __syncthreads();
    const int K = s_K;

    if (t < K) {
        float sc = ep.k_score[t]; short id = ep.k_idx[t];
        int rank = 0;
        for (int j = 0; j < K; ++j) {
            float sj = ep.k_score[j];
            rank += (sj > sc) || (sj == sc && ep.k_idx[j] < id);
        }
        if (rank < MAXI) {
            int ee = ep.k_ent[t];
            float4 b4 = ep.box[ee];
            ep.outbuf[rank * 6 + 0] = b4.x;
            ep.outbuf[rank * 6 + 1] = b4.y;
            ep.outbuf[rank * 6 + 2] = b4.z;
            ep.outbuf[rank * 6 + 3] = b4.w;
            ep.outbuf[rank * 6 + 4] = (float)ep.cls[ee];
            ep.outbuf[rank * 6 + 5] = sc;
        }
    }
    __syncthreads();

    float* ob = out + (size_t)img * MAXI * 6;
    for (int o = t; o < MAXI * 6; o += BT) ob[o] = ep.outbuf[o];

    if (t == 0) { g_cnt[img] = 0; g_done[img] = 0; g_done2[img] = 0; }
}

extern "C" void kernel_launch(void* const* d_in, const int* in_sizes, int n_in,
                              void* d_out, int out_size)
{
    const float* rois    = (const float*)d_in[0];
    const float* probs   = (const float*)d_in[1];
    const float* bbox    = (const float*)d_in[2];
    const float* std_dev = (const float*)d_in[3];
    float* out = (float*)d_out;
    det_kernel<<<BATCH * BPI, BT>>>(rois, probs, bbox, std_dev, out);
}

// round 17
// speedup vs baseline: 2.0441x; 2.0441x over previous
#include <cuda_runtime.h>
#include <math.h>

#define BATCH 32
#define NROI 1000
#define NCLS 81
#define MAXI 100
#define NTOT (BATCH * NROI)
#define BTA 128
#define BT2 1024
#define FULL 0xffffffffu

// compacted per-image lists (zero-init; g_cnt reset by kernel B each run)
__device__ float4 g_cbox[NTOT];
__device__ float4 g_cmeta[NTOT];   // {score, cls, origidx, 0}
__device__ int    g_cnt[BATCH];

// ---------------------------------------------------------------------------
// Kernel A: direct vectorized thread-per-ROI argmax (no smem, no barriers)
// ---------------------------------------------------------------------------
__global__ __launch_bounds__(BTA)
void detA_kernel(const float* __restrict__ rois,
                 const float* __restrict__ probs,
                 const float* __restrict__ bbox,
                 const float* __restrict__ std_dev)
{
    const int tid = blockIdx.x * BTA + threadIdx.x;    // 0..31999 (exact)
    const int img = tid / NROI;
    const int r   = tid - img * NROI;

    const int f0 = tid * NCLS;            // float index of row start (< 2.6M)
    const int s  = f0 & 3;                // 0..3
    const float4* w = (const float4*)(probs + (f0 - s));   // 16B aligned

    // 21 independent LDG.128s cover floats [f0-s, f0-s+84) ⊇ the 81-float row.
    // In-bounds proof: end = f0 - s + 84 = (f0+81) + (3-s); the only row with
    // f0+81 == total (t=31999) has s==3, so end == total exactly.
    float v[84];
    #pragma unroll
    for (int k = 0; k < 21; ++k) {
        float4 q = w[k];
        v[4 * k + 0] = q.x;
        v[4 * k + 1] = q.y;
        v[4 * k + 2] = q.z;
        v[4 * k + 3] = q.w;
    }

    // unrolled first-max over positions p in [s, s+81); class = p - s
    float best = -INFINITY;
    int bp = 0;
    #pragma unroll
    for (int p = 0; p < 84; ++p) {
        bool ok = (p >= s) && (p < s + 81);
        if (ok && v[p] > best) { best = v[p]; bp = p; }
    }
    const int bi = bp - s;

    if (bi > 0 && best >= 0.7f) {
        const float4 sd = *(const float4*)std_dev;
        const float4 dv = *(const float4*)(bbox + ((size_t)tid * NCLS + bi) * 4);
        const float4 ro = *(const float4*)(rois + (size_t)tid * 4);

        float d0 = dv.x * sd.x, d1 = dv.y * sd.y, d2 = dv.z * sd.z, d3 = dv.w * sd.w;
        float hh = ro.z - ro.x;
        float ww = ro.w - ro.y;
        float cy = ro.x + 0.5f * hh + d0 * hh;
        float cx = ro.y + 0.5f * ww + d1 * ww;
        hh *= expf(d2);
        ww *= expf(d3);
        float ny1 = cy - 0.5f * hh;
        float nx1 = cx - 0.5f * ww;
        float ny2 = ny1 + hh;
        float nx2 = nx1 + ww;
        ny1 = fminf(fmaxf(ny1, 0.0f), 1.0f);
        nx1 = fminf(fmaxf(nx1, 0.0f), 1.0f);
        ny2 = fminf(fmaxf(ny2, 0.0f), 1.0f);
        nx2 = fminf(fmaxf(nx2, 0.0f), 1.0f);

        int pos = atomicAdd(&g_cnt[img], 1);
        if (pos < NROI) {
            g_cbox[img * NROI + pos]  = make_float4(ny1, nx1, ny2, nx2);
            g_cmeta[img * NROI + pos] = make_float4(best, (float)bi, (float)r, 0.0f);
        }
    }
}

// ---------------------------------------------------------------------------
// Kernel B: R14's proven minimal-chain epilogue (grid 32, 1024 threads)
// ---------------------------------------------------------------------------
__global__ __launch_bounds__(BT2)
void detB_kernel(float* __restrict__ out)
{
    __shared__ float  s_score[NROI];
    __shared__ short  s_idx[NROI];
    __shared__ short  s_cls[NROI];
    __shared__ float4 s_box[NROI];
    __shared__ short  s_perm[NROI];
    __shared__ short  s_sort[NROI];
    __shared__ unsigned char s_kp[NROI];
    __shared__ int    s_ccount[NCLS];
    __shared__ int    s_cstart[NCLS];
    __shared__ int    s_ccur[NCLS];
    __shared__ float  k_score[NROI];
    __shared__ short  k_idx[NROI];
    __shared__ short  k_ent[NROI];
    __shared__ float  s_out[MAXI * 6];
    __shared__ int    s_wsum[32];
    __shared__ int    s_K;

    const int b = blockIdx.x;
    const int t = threadIdx.x;
    const int wid = t >> 5;
    const int lane = t & 31;
    const int base = b * NROI;
    const int M = min(g_cnt[b], NROI);

    if (t < NCLS) { s_ccount[t] = 0; s_ccur[t] = 0; }
    for (int o = t; o < MAXI * 6; o += BT2) s_out[o] = 0.0f;

    int mycls = -1;
    if (t < M) {
        float4 m  = g_cmeta[base + t];
        float4 bx = g_cbox[base + t];
        s_score[t] = m.x;
        s_cls[t]   = (short)m.y;
        s_idx[t]   = (short)m.z;
        s_box[t]   = bx;
        mycls = (int)m.y;
    }
    __syncthreads();
    if (mycls >= 0) atomicAdd(&s_ccount[mycls], 1);
    __syncthreads();

    if (wid == 0) {
        const int c0 = lane, c1 = lane + 32, c2 = lane + 64;
        int v0 = s_ccount[c0];
        int v1 = (c1 < NCLS) ? s_ccount[c1] : 0;
        int v2 = (c2 < NCLS) ? s_ccount[c2] : 0;
        int i0 = v0, i1 = v1, i2 = v2;
        #pragma unroll
        for (int off = 1; off < 32; off <<= 1) {
            int n0 = __shfl_up_sync(FULL, i0, off);
            int n1 = __shfl_up_sync(FULL, i1, off);
            int n2 = __shfl_up_sync(FULL, i2, off);
            if (lane >= off) { i0 += n0; i1 += n1; i2 += n2; }
        }
        const int tot0 = __shfl_sync(FULL, i0, 31);
        const int tot1 = __shfl_sync(FULL, i1, 31);
        s_cstart[c0] = i0 - v0;
        if (c1 < NCLS) s_cstart[c1] = tot0 + i1 - v1;
        if (c2 < NCLS) s_cstart[c2] = tot0 + tot1 + i2 - v2;
    }
    __syncthreads();

    if (mycls >= 0) {
        int p = s_cstart[mycls] + atomicAdd(&s_ccur[mycls], 1);
        s_perm[p] = (short)t;
    }
    __syncthreads();

    for (int c = wid; c < NCLS; c += 32) {
        const int cs = s_cstart[c];
        const int n  = s_ccount[c];
        if (n <= 0) continue;
        if (n <= 32) {
            const bool v = (lane < n);
            int e = 0; float sc = -1.0f, idf = 1e9f;
            float4 bb = make_float4(0.f, 0.f, 0.f, 0.f);
            if (v) {
                e = s_perm[cs + lane];
                sc = s_score[e]; idf = (float)s_idx[e];
                bb = s_box[e];
            }
            int rank = v ? 0 : 999;
            for (int m2 = 0; m2 < n; ++m2) {
                float s2 = __shfl_sync(FULL, sc,  m2);
                float i2 = __shfl_sync(FULL, idf, m2);
                if (v) rank += (s2 > sc) || (s2 == sc && i2 < idf);
            }
            int keep = v ? 1 : 0;
            float area = (bb.z - bb.x) * (bb.w - bb.y);
            for (int a = 0; a < n - 1; ++a) {
                unsigned am = __ballot_sync(FULL, rank == a);
                int src = __ffs(am) - 1;
                int ks  = __shfl_sync(FULL, keep, src);
                float sy1 = __shfl_sync(FULL, bb.x, src);
                float sx1 = __shfl_sync(FULL, bb.y, src);
                float sy2 = __shfl_sync(FULL, bb.z, src);
                float sx2 = __shfl_sync(FULL, bb.w, src);
                float sa  = __shfl_sync(FULL, area, src);
                if (ks && keep && rank > a) {
                    float ih = fmaxf(fminf(sy2, bb.z) - fmaxf(sy1, bb.x), 0.0f);
                    float iw = fmaxf(fminf(sx2, bb.w) - fmaxf(sx1, bb.y), 0.0f);
                    float inter = ih * iw;
                    float iou = inter / fmaxf(sa + area - inter, 1e-8f);
                    if (iou > 0.3f) keep = 0;
                }
            }
            if (v) { s_sort[cs + rank] = (short)e; s_kp[cs + rank] = (unsigned char)keep; }
        } else {
            for (int p = lane; p < n; p += 32) {
                int e = s_perm[cs + p];
                float sc = s_score[e]; short id = s_idx[e];
                int rank = 0;
                for (int j = 0; j < n; ++j) {
                    int ej = s_perm[cs + j];
                    float sj = s_score[ej];
                    rank += (sj > sc) || (sj == sc && s_idx[ej] < id);
                }
                s_sort[cs + rank] = (short)e;
                s_kp[cs + rank] = 1;
            }
            __syncwarp();
            for (int a = 0; a < n - 1; ++a) {
                if (!s_kp[cs + a]) continue;
                int ea = s_sort[cs + a];
                float4 ba = s_box[ea];
                float aa = (ba.z - ba.x) * (ba.w - ba.y);
                for (int q = a + 1 + lane; q < n; q += 32) {
                    if (!s_kp[cs + q]) continue;
                    int eq = s_sort[cs + q];
                    float4 bq = s_box[eq];
                    float ab = (bq.z - bq.x) * (bq.w - bq.y);
                    float ih = fmaxf(fminf(ba.z, bq.z) - fmaxf(ba.x, bq.x), 0.0f);
                    float iw = fmaxf(fminf(ba.w, bq.w) - fmaxf(ba.y, bq.y), 0.0f);
                    float inter = ih * iw;
                    float iou = inter / fmaxf(aa + ab - inter, 1e-8f);
                    if (iou > 0.3f) s_kp[cs + q] = 0;
                }
                __syncwarp();
            }
        }
    }
    __syncthreads();

    int kflag = 0; int e = -1;
    if (t < M && s_kp[t]) { kflag = 1; e = s_sort[t]; }
    {
        unsigned mask = __ballot_sync(FULL, kflag);
        if (lane == 0) s_wsum[wid] = __popc(mask);
        __syncthreads();
        if (wid == 0) {
            int v = s_wsum[lane];
            int inc = v;
            #pragma unroll
            for (int off = 1; off < 32; off <<= 1) {
                int nn = __shfl_up_sync(FULL, inc, off);
                if (lane >= off) inc += nn;
            }
            s_wsum[lane] = inc - v;
            if (lane == 31) s_K = inc;
        }
        __syncthreads();
        int slot = s_wsum[wid] + __popc(mask & ((1u << lane) - 1));
        if (kflag) {
            k_score[slot] = s_score[e];
            k_idx[slot]   = s_idx[e];
            k_ent[slot]   = (short)e;
        }
    }
    __syncthreads();
    const int K = s_K;

    if (t < K) {
        float sc = k_score[t]; short id = k_idx[t];
        int rank = 0;
        for (int j = 0; j < K; ++j) {
            float sj = k_score[j];
            rank += (sj > sc) || (sj == sc && k_idx[j] < id);
        }
        if (rank < MAXI) {
            int ee = k_ent[t];
            float4 b4 = s_box[ee];
            s_out[rank * 6 + 0] = b4.x;
            s_out[rank * 6 + 1] = b4.y;
            s_out[rank * 6 + 2] = b4.z;
            s_out[rank * 6 + 3] = b4.w;
            s_out[rank * 6 + 4] = (float)s_cls[ee];
            s_out[rank * 6 + 5] = sc;
        }
    }
    __syncthreads();

    float* ob = out + (size_t)b * MAXI * 6;
    for (int o = t; o < MAXI * 6; o += BT2) ob[o] = s_out[o];

    if (t == 0) g_cnt[b] = 0;   // reset for next graph replay
}

extern "C" void kernel_launch(void* const* d_in, const int* in_sizes, int n_in,
                              void* d_out, int out_size)
{
    const float* rois    = (const float*)d_in[0];
    const float* probs   = (const float*)d_in[1];
    const float* bbox    = (const float*)d_in[2];
    const float* std_dev = (const float*)d_in[3];
    float* out = (float*)d_out;

    detA_kernel<<<NTOT / BTA, BTA>>>(rois, probs, bbox, std_dev);   // 250 blocks
    detB_kernel<<<BATCH, BT2>>>(out);
}